// round 16
// baseline (speedup 1.0000x reference)
#include <cuda_runtime.h>
#include <cuda_fp16.h>
#include <math.h>
#include <stdint.h>

#define HWSZ 50176           // 224*224
#define BB   4
#define CC   256
#define KP   264             // padded row stride (fp16): 528B = 33*16B
#define KPB  528

// ================= scratch (device globals) =================
__device__ __half g_qkv[(size_t)BB * HWSZ * 768];   // pixel-major [B][HW][768]
__device__ __half g_psi[(size_t)BB * HWSZ * CC];    // [B][HW][256]
__device__ __half g_gk [(size_t)BB * HWSZ * CC];    // pre-gated K (kg)
__device__ __half g_gv [(size_t)BB * HWSZ * CC];    // pre-gated V (vg)
__device__ float  g_mean[BB * CC];
__device__ float  g_cvec[BB * CC];
// fp16 padded operands [B][HW][KP]
__device__ __half g_ta[(size_t)BB * HWSZ * KP];
__device__ __half g_tb[(size_t)BB * HWSZ * KP];
__device__ __half g_tc[(size_t)BB * HWSZ * KP];
__device__ __half g_td[(size_t)BB * HWSZ * KP];
// padded fp16 weights: [qkv 768 | k1 256 | v1 256 | k2 | v2 | p2 | out] x KP
__device__ __half g_wp[2304 * KP];

// ================= PTX helpers =================
__device__ __forceinline__ uint32_t smem_u32(const void* p) {
    uint32_t a;
    asm("{ .reg .u64 t; cvta.to.shared.u64 t, %1; cvt.u32.u64 %0, t; }" : "=r"(a) : "l"(p));
    return a;
}
__device__ __forceinline__ void mbar_init(uint32_t a, uint32_t cnt) {
    asm volatile("mbarrier.init.shared.b64 [%0], %1;" :: "r"(a), "r"(cnt) : "memory");
}
__device__ __forceinline__ void expect_tx(uint32_t mbar, uint32_t bytes) {
    asm volatile("mbarrier.arrive.expect_tx.shared.b64 _, [%0], %1;" :: "r"(mbar), "r"(bytes) : "memory");
}
__device__ __forceinline__ void bulk_g2s(uint32_t dst, const void* src, uint32_t bytes, uint32_t mbar) {
    asm volatile("cp.async.bulk.shared::cluster.global.mbarrier::complete_tx::bytes [%0], [%1], %2, [%3];"
                 :: "r"(dst), "l"(src), "r"(bytes), "r"(mbar) : "memory");
}
__device__ __forceinline__ void mbar_wait(uint32_t mbar, uint32_t parity) {
    asm volatile(
        "{\n\t.reg .pred P;\n"
        "W_%=:\n\t"
        "mbarrier.try_wait.parity.acquire.cta.shared::cta.b64 P, [%0], %1, 0x989680;\n\t"
        "@P bra D_%=;\n\t"
        "bra W_%=;\n"
        "D_%=:\n\t}"
        :: "r"(mbar), "r"(parity) : "memory");
}
#define LDSM4(r0, r1, r2, r3, addr) \
    asm volatile("ldmatrix.sync.aligned.m8n8.x4.shared.b16 {%0,%1,%2,%3}, [%4];" \
                 : "=r"(r0), "=r"(r1), "=r"(r2), "=r"(r3) : "r"(addr))
__device__ __forceinline__ void mma_f16(float* c, const uint32_t* a, uint32_t b0, uint32_t b1) {
    asm volatile(
        "mma.sync.aligned.m16n8k16.row.col.f32.f16.f16.f32 "
        "{%0,%1,%2,%3}, {%4,%5,%6,%7}, {%8,%9}, {%0,%1,%2,%3};"
        : "+f"(c[0]), "+f"(c[1]), "+f"(c[2]), "+f"(c[3])
        : "r"(a[0]), "r"(a[1]), "r"(a[2]), "r"(a[3]), "r"(b0), "r"(b1));
}
__device__ __forceinline__ float sigmoidf_(float x) { return 1.f / (1.f + __expf(-x)); }

// ================= small kernels =================
__global__ void mean_kernel(const float* __restrict__ G, float* __restrict__ out) {
    const int bc = blockIdx.x;
    const float4* p = (const float4*)(G + (size_t)bc * HWSZ);
    float s = 0.f;
    for (int i = threadIdx.x; i < HWSZ / 4; i += blockDim.x) {
        float4 v = p[i];
        s += (v.x + v.y) + (v.z + v.w);
    }
    __shared__ float sm[256];
    sm[threadIdx.x] = s;
    __syncthreads();
    for (int k = 128; k > 0; k >>= 1) {
        if (threadIdx.x < k) sm[threadIdx.x] += sm[threadIdx.x + k];
        __syncthreads();
    }
    if (threadIdx.x == 0) out[bc] = sm[0] * (1.f / HWSZ);
}

__global__ void cvec_kernel(const float* __restrict__ Wout, const float* __restrict__ bout,
                            const float* __restrict__ gmean, float* __restrict__ cvec) {
    __shared__ float gm[CC];
    const int b = blockIdx.x, oc = threadIdx.x;
    gm[oc] = gmean[b * CC + oc];
    __syncthreads();
    float s = 0.f;
    #pragma unroll 8
    for (int c = 0; c < CC; ++c) s += Wout[(size_t)oc * CC + c] * gm[c];
    cvec[b * CC + oc] = 0.5f * s + bout[oc];
}

// fp32 weights [rows][256] -> padded fp16 [rows][KP] (pad zeroed)
__global__ void wconv(const float* __restrict__ W, __half* __restrict__ o) {
    const int row = blockIdx.x, k = threadIdx.x;
    o[(size_t)row * KP + k]       = __float2half(W[(size_t)row * 256 + k]);
    o[(size_t)row * KP + k + 128] = __float2half(W[(size_t)row * 256 + k + 128]);
    if (k < KP - 256) o[(size_t)row * KP + 256 + k] = __float2half(0.f);
}

// transpose fp32 X[b][C][HW] -> fp16 padded T[b][HW][KP]
__global__ void tconv(const float* __restrict__ X, __half* __restrict__ T) {
    __shared__ float t[32][33];
    const int b = blockIdx.z, k0 = blockIdx.y * 32, p0 = blockIdx.x * 32;
    const int tx = threadIdx.x, ty = threadIdx.y;
    const float* src = X + ((size_t)b * CC + k0) * HWSZ + p0;
    #pragma unroll
    for (int r = 0; r < 4; ++r)
        t[ty + r * 8][tx] = src[(size_t)(ty + r * 8) * HWSZ + tx];
    __syncthreads();
    #pragma unroll
    for (int r = 0; r < 4; ++r) {
        const int p = ty + r * 8;
        T[((size_t)b * HWSZ + p0 + p) * KP + k0 + tx] = __float2half(t[tx][p]);
    }
}

// ================= bulk-copy HMMA GEMM: split warp-group pipeline =================
enum { EPI_QKV_T = 0, EPI_RELU_T = 1, EPI_SIG_T = 2, EPI_SIG_GATE_T = 3, EPI_OUT = 4 };

#define A_BYTES  (128 * KPB)        // 67584
#define XC_ROWS  32
#define XC_BYTES (XC_ROWS * KPB)    // 16896
#define SM_X0    A_BYTES
#define MB_OFF   (A_BYTES + 2 * XC_BYTES)   // 101376
#define SMEM_TOTAL (MB_OFF + 32)

template<int EPI, bool SWAP, int NCH, bool GENA>
__global__ void __launch_bounds__(256, 2)
gemm_bulk(const __half* __restrict__ A_, const __half* __restrict__ B_,
          const float* __restrict__ bias, const __half* __restrict__ gate,
          const float* __restrict__ cvec, float* __restrict__ Yf,
          __half* __restrict__ Yh, int OS,
          const float* __restrict__ bias2, __half* __restrict__ Yh2,
          const float* __restrict__ gaV, const float* __restrict__ gaW,
          const float* __restrict__ gaB,
          const __half* __restrict__ kvsrc)    // EPI_SIG_GATE_T: qkvT section (stride 768)
{
    extern __shared__ char dsm[];
    const uint32_t smb = smem_u32(dsm);
    const int b = blockIdx.z;
    const int tid = threadIdx.x, wid = tid >> 5, lane = tid & 31;
    const int g = lane >> 2, t = lane & 3;
    const int grp = wid >> 2;          // warp group 0/1
    const int warpM = wid & 3;

    const size_t arow0 = SWAP ? ((size_t)b * HWSZ + (size_t)blockIdx.y * 128)
                              : (size_t)blockIdx.y * 128;
    const size_t brow0 = SWAP ? 0 : ((size_t)b * HWSZ + (size_t)blockIdx.x * (NCH * XC_ROWS));
    const __half* Ab = A_ + arow0 * KP;
    const __half* Bb = B_ + brow0 * KP;

    const uint32_t mbw = smb + MB_OFF;
    const uint32_t mbx = smb + MB_OFF + 8 + (uint32_t)grp * 8;   // group's stage barrier
    if (tid == 0) {
        mbar_init(mbw, 1);
        mbar_init(smb + MB_OFF + 8, 1);
        mbar_init(smb + MB_OFF + 16, 1);
    }
    __syncthreads();
    if (tid == 0) {
        if (!GENA) { expect_tx(mbw, A_BYTES); bulk_g2s(smb, Ab, A_BYTES, mbw); }
        expect_tx(smb + MB_OFF + 8,  XC_BYTES); bulk_g2s(smb + SM_X0,            Bb,                XC_BYTES, smb + MB_OFF + 8);
        expect_tx(smb + MB_OFF + 16, XC_BYTES); bulk_g2s(smb + SM_X0 + XC_BYTES, Bb + XC_ROWS * KP, XC_BYTES, smb + MB_OFF + 16);
    }

    // ldmatrix addresses (528B row stride -> conflict-free)
    const int l7 = lane & 7;
    const uint32_t rowA0 = (uint32_t)(warpM * 32 + l7 + ((lane >> 3) & 1) * 8);
    const uint32_t aA0 = smb + rowA0 * KPB + ((lane >> 4) & 1) * 16;
    const uint32_t aA1 = aA0 + 16 * KPB;
    const uint32_t xb = smb + SM_X0 + (uint32_t)grp * XC_BYTES;  // group's dedicated stage
    const uint32_t rowB0 = (uint32_t)(l7 + ((lane >> 4) & 1) * 8);
    const uint32_t bB0 = xb + rowB0 * KPB + ((lane >> 3) & 1) * 16;
    const uint32_t bB1 = bB0 + 16 * KPB;

    if (GENA) {
        const int r = tid & 127, hf = tid >> 7;
        const float v = gaV[(size_t)b * HWSZ + (size_t)blockIdx.y * 128 + r];
        const int k0 = hf * 132;
        #pragma unroll 1
        for (int kk = 0; kk < 66; ++kk) {
            const int k = k0 + kk * 2;
            float x0 = 0.f, x1 = 0.f;
            if (k < 256) {
                x0 = fmaxf(v * gaW[k]     + gaB[k],     0.f);
                x1 = fmaxf(v * gaW[k + 1] + gaB[k + 1], 0.f);
            }
            __half2 hh; hh.x = __float2half(x0); hh.y = __float2half(x1);
            *(__half2*)(dsm + (size_t)r * KPB + (size_t)k * 2) = hh;
        }
        __syncthreads();
    } else {
        mbar_wait(mbw, 0);
    }

    int ph = 0;
    #pragma unroll 1
    for (int c = grp; c < NCH; c += 2) {
        mbar_wait(mbx, ph);
        ph ^= 1;

        float acc[2][4][4];
        #pragma unroll
        for (int mi = 0; mi < 2; ++mi)
            #pragma unroll
            for (int ni = 0; ni < 4; ++ni)
                #pragma unroll
                for (int u = 0; u < 4; ++u) acc[mi][ni][u] = 0.f;

        #pragma unroll
        for (int k16 = 0; k16 < 16; ++k16) {
            const uint32_t ko = (uint32_t)k16 * 32;
            uint32_t a0[4], a1[4], f0[4], f1[4];
            LDSM4(a0[0], a0[1], a0[2], a0[3], aA0 + ko);
            LDSM4(a1[0], a1[1], a1[2], a1[3], aA1 + ko);
            LDSM4(f0[0], f0[1], f0[2], f0[3], bB0 + ko);
            LDSM4(f1[0], f1[1], f1[2], f1[3], bB1 + ko);
            mma_f16(acc[0][0], a0, f0[0], f0[1]);
            mma_f16(acc[0][1], a0, f0[2], f0[3]);
            mma_f16(acc[0][2], a0, f1[0], f1[1]);
            mma_f16(acc[0][3], a0, f1[2], f1[3]);
            mma_f16(acc[1][0], a1, f0[0], f0[1]);
            mma_f16(acc[1][1], a1, f0[2], f0[3]);
            mma_f16(acc[1][2], a1, f1[0], f1[1]);
            mma_f16(acc[1][3], a1, f1[2], f1[3]);
        }

        asm volatile("bar.sync %0, 128;" :: "r"(grp + 1) : "memory");
        if (c + 2 < NCH && tid == grp * 128) {
            expect_tx(mbx, XC_BYTES);
            bulk_g2s(xb, Bb + (size_t)(c + 2) * XC_ROWS * KP, XC_BYTES, mbx);
        }

        const int nbase = c * XC_ROWS;
        #pragma unroll
        for (int mi = 0; mi < 2; ++mi) {
            #pragma unroll
            for (int r2 = 0; r2 < 2; ++r2) {
                const int m = warpM * 32 + mi * 16 + g + r2 * 8;
                if (!SWAP) {
                    const int oc = (int)blockIdx.y * 128 + m;
                    const float cv = cvec[b * CC + oc];
                    const size_t ybase = ((size_t)b * CC + oc) * HWSZ + (size_t)blockIdx.x * (NCH * XC_ROWS);
                    #pragma unroll
                    for (int ni = 0; ni < 4; ++ni) {
                        const int n = nbase + ni * 8 + t * 2;
                        float2 r;
                        r.x = 0.5f * acc[mi][ni][r2 * 2 + 0] + cv;
                        r.y = 0.5f * acc[mi][ni][r2 * 2 + 1] + cv;
                        *(float2*)(Yf + ybase + n) = r;
                    }
                } else {
                    const size_t prow = (size_t)b * HWSZ + (size_t)blockIdx.y * 128 + m;
                    if (EPI == EPI_RELU_T) {
                        #pragma unroll
                        for (int ni = 0; ni < 4; ++ni) {
                            const int oc = nbase + ni * 8 + t * 2;
                            const float* bp = bias;
                            __half* yp = Yh;
                            int o2 = oc;
                            if (oc >= 256) { bp = bias2; yp = Yh2; o2 = oc - 256; }
                            float v0 = fmaxf(acc[mi][ni][r2 * 2 + 0] + bp[o2], 0.f);
                            float v1 = fmaxf(acc[mi][ni][r2 * 2 + 1] + bp[o2 + 1], 0.f);
                            __half2 r; r.x = __float2half(v0); r.y = __float2half(v1);
                            *(__half2*)(yp + prow * KP + o2) = r;
                        }
                    } else {
                        #pragma unroll
                        for (int ni = 0; ni < 4; ++ni) {
                            const int oc = nbase + ni * 8 + t * 2;
                            float v0 = acc[mi][ni][r2 * 2 + 0] + bias[oc];
                            float v1 = acc[mi][ni][r2 * 2 + 1] + bias[oc + 1];
                            if (EPI == EPI_SIG_T) { v0 = sigmoidf_(v0); v1 = sigmoidf_(v1); }
                            else if (EPI == EPI_SIG_GATE_T) {
                                __half2 gg = *(const __half2*)(gate + prow * CC + oc);
                                // pre-gated output: gate * K (or V) from qkvT
                                __half2 kk = *(const __half2*)(kvsrc + prow * 768 + oc);
                                v0 = sigmoidf_(v0) * (1.f - __half2float(gg.x)) * __half2float(kk.x);
                                v1 = sigmoidf_(v1) * (1.f - __half2float(gg.y)) * __half2float(kk.y);
                            }
                            __half2 r; r.x = __float2half(v0); r.y = __float2half(v1);
                            *(__half2*)(Yh + prow * OS + oc) = r;
                        }
                    }
                }
            }
        }
    }
}

// ================= windowed attention (R12 tiles; pre-gated K/V inputs) =================
__global__ void __launch_bounds__(128)
attn_kernel(const __half* __restrict__ qkvT, const __half* __restrict__ kgT,
            const __half* __restrict__ vgT, __half* __restrict__ ft)
{
    const int w = blockIdx.x, h = blockIdx.y;
    const int b = w >> 10, wy = (w >> 5) & 31, wx = w & 31;
    const int tid = threadIdx.x;

    __shared__ float Qs[49 * 33];
    __shared__ float Ks[49 * 33];
    __shared__ float Vs[49 * 33];
    __shared__ float S [49 * 49];

    const int row0 = wy * 7, col0 = wx * 7;
    const int hoff = h * 32;

    for (int e = tid; e < 49 * 16; e += 128) {
        const int n = e >> 4, d2 = (e & 15) << 1;
        const int hw = (row0 + n / 7) * 224 + col0 + (n % 7);
        const size_t pb = (size_t)b * HWSZ + hw;
        const __half2 q2 = *(const __half2*)(qkvT + pb * 768 + hoff + d2);
        const __half2 k2 = *(const __half2*)(kgT + pb * CC + hoff + d2);
        const __half2 v2 = *(const __half2*)(vgT + pb * CC + hoff + d2);
        Qs[n * 33 + d2]     = __half2float(q2.x);
        Qs[n * 33 + d2 + 1] = __half2float(q2.y);
        Ks[n * 33 + d2]     = __half2float(k2.x);
        Ks[n * 33 + d2 + 1] = __half2float(k2.y);
        Vs[n * 33 + d2]     = __half2float(v2.x);
        Vs[n * 33 + d2 + 1] = __half2float(v2.y);
    }
    __syncthreads();

    const float scale = 0.17677669529663687f;   // 32^-0.5

    // ---- QK^T: 7x4 register tiles, 91 threads (R12) ----
    if (tid < 91) {
        const int i0 = (tid / 13) * 7;
        const int j0 = (tid % 13) * 4;
        float acc[7][4];
        #pragma unroll
        for (int r = 0; r < 7; ++r)
            #pragma unroll
            for (int c2 = 0; c2 < 4; ++c2) acc[r][c2] = 0.f;
        int jc[4];
        #pragma unroll
        for (int c2 = 0; c2 < 4; ++c2) jc[c2] = min(j0 + c2, 48);
        #pragma unroll
        for (int d = 0; d < 32; ++d) {
            float kv[4];
            #pragma unroll
            for (int c2 = 0; c2 < 4; ++c2) kv[c2] = Ks[jc[c2] * 33 + d];
            #pragma unroll
            for (int r = 0; r < 7; ++r) {
                const float qv = Qs[(i0 + r) * 33 + d];
                #pragma unroll
                for (int c2 = 0; c2 < 4; ++c2) acc[r][c2] += qv * kv[c2];
            }
        }
        #pragma unroll
        for (int r = 0; r < 7; ++r)
            #pragma unroll
            for (int c2 = 0; c2 < 4; ++c2)
                if (j0 + c2 < 49) S[(i0 + r) * 49 + j0 + c2] = acc[r][c2] * scale;
    }
    __syncthreads();

    // ---- softmax: one row per thread ----
    if (tid < 49) {
        float m = -1e30f;
        for (int j = 0; j < 49; ++j) m = fmaxf(m, S[tid * 49 + j]);
        float sum = 0.f;
        for (int j = 0; j < 49; ++j) {
            float ev = __expf(S[tid * 49 + j] - m);
            S[tid * 49 + j] = ev;
            sum += ev;
        }
        const float inv = 1.f / sum;
        for (int j = 0; j < 49; ++j) S[tid * 49 + j] *= inv;
    }
    __syncthreads();

    // ---- S @ V: 4x4 register tiles, 104 threads (R12) ----
    if (tid < 104) {
        const int n0 = (tid / 8) * 4;
        const int d0 = (tid & 7) * 4;
        float acc[4][4];
        #pragma unroll
        for (int r = 0; r < 4; ++r)
            #pragma unroll
            for (int c2 = 0; c2 < 4; ++c2) acc[r][c2] = 0.f;
        int nr[4];
        #pragma unroll
        for (int r = 0; r < 4; ++r) nr[r] = min(n0 + r, 48);
        #pragma unroll 7
        for (int m2 = 0; m2 < 49; ++m2) {
            float vv[4];
            #pragma unroll
            for (int c2 = 0; c2 < 4; ++c2) vv[c2] = Vs[m2 * 33 + d0 + c2];
            #pragma unroll
            for (int r = 0; r < 4; ++r) {
                const float sv = S[nr[r] * 49 + m2];
                #pragma unroll
                for (int c2 = 0; c2 < 4; ++c2) acc[r][c2] += sv * vv[c2];
            }
        }
        #pragma unroll
        for (int r = 0; r < 4; ++r) {
            const int n = n0 + r;
            if (n < 49) {
                const int hw = (row0 + n / 7) * 224 + col0 + (n % 7);
                #pragma unroll
                for (int c2 = 0; c2 < 4; ++c2)
                    ft[((size_t)b * HWSZ + hw) * KP + hoff + d0 + c2] = __float2half(acc[r][c2]);
            }
        }
    }
}

// ================= launcher =================
extern "C" void kernel_launch(void* const* d_in, const int* in_sizes, int n_in,
                              void* d_out, int out_size) {
    (void)in_sizes; (void)n_in; (void)out_size;
    const float* G    = (const float*)d_in[0];
    const float* Vin  = (const float*)d_in[2];
    const float* Z    = (const float*)d_in[3];
    const float* Wqkv = (const float*)d_in[4];
    const float* bqkv = (const float*)d_in[5];
    const float* Wout = (const float*)d_in[6];
    const float* bout = (const float*)d_in[7];
    const float* Wk1  = (const float*)d_in[8];
    const float* bk1  = (const float*)d_in[9];
    const float* Wk2  = (const float*)d_in[10];
    const float* bk2  = (const float*)d_in[11];
    const float* Wv1  = (const float*)d_in[12];
    const float* bv1  = (const float*)d_in[13];
    const float* Wv2  = (const float*)d_in[14];
    const float* bv2  = (const float*)d_in[15];
    const float* Wp1  = (const float*)d_in[16];
    const float* bp1  = (const float*)d_in[17];
    const float* Wp2  = (const float*)d_in[18];
    const float* bp2  = (const float*)d_in[19];
    float* out = (float*)d_out;

    __half *qkvT, *psiT, *kgT, *vgT, *ta, *tb, *tc, *td, *wp;
    float *gmean, *cvec;
    cudaGetSymbolAddress((void**)&qkvT,  g_qkv);
    cudaGetSymbolAddress((void**)&psiT,  g_psi);
    cudaGetSymbolAddress((void**)&kgT,   g_gk);
    cudaGetSymbolAddress((void**)&vgT,   g_gv);
    cudaGetSymbolAddress((void**)&gmean, g_mean);
    cudaGetSymbolAddress((void**)&cvec,  g_cvec);
    cudaGetSymbolAddress((void**)&ta,    g_ta);
    cudaGetSymbolAddress((void**)&tb,    g_tb);
    cudaGetSymbolAddress((void**)&tc,    g_tc);
    cudaGetSymbolAddress((void**)&td,    g_td);
    cudaGetSymbolAddress((void**)&wp,    g_wp);

    cudaFuncSetAttribute(gemm_bulk<EPI_QKV_T,      true,  24, false>, cudaFuncAttributeMaxDynamicSharedMemorySize, SMEM_TOTAL);
    cudaFuncSetAttribute(gemm_bulk<EPI_RELU_T,     true,  16, false>, cudaFuncAttributeMaxDynamicSharedMemorySize, SMEM_TOTAL);
    cudaFuncSetAttribute(gemm_bulk<EPI_SIG_T,      true,  8,  true>,  cudaFuncAttributeMaxDynamicSharedMemorySize, SMEM_TOTAL);
    cudaFuncSetAttribute(gemm_bulk<EPI_SIG_GATE_T, true,  8,  false>, cudaFuncAttributeMaxDynamicSharedMemorySize, SMEM_TOTAL);
    cudaFuncSetAttribute(gemm_bulk<EPI_OUT,        false, 8,  false>, cudaFuncAttributeMaxDynamicSharedMemorySize, SMEM_TOTAL);

    // weight layout (rows of KP)
    __half* wQKV = wp;
    __half* wKV1 = wp + (size_t)768  * KP;   // k1 rows [0,256), v1 rows [256,512)
    __half* wK2  = wp + (size_t)1280 * KP;
    __half* wV2  = wp + (size_t)1536 * KP;
    __half* wP2  = wp + (size_t)1792 * KP;
    __half* wOUT = wp + (size_t)2048 * KP;

    const dim3 tgrid(HWSZ / 32, CC / 32, BB), tblk(32, 8);
    const dim3 gS(1, 392, BB);    // SWAP: px-tiles(128) on y
    const dim3 gO(196, 2, BB);    // !SWAP out: px-tiles(256) x oc-tiles(128) x B

    // launch order: index 3 = qkv GEMM (ncu profiled slot)
    tconv<<<tgrid, tblk>>>(G, ta);                              // 0
    wconv<<<768, 128>>>(Wqkv, wQKV);                            // 1
    mean_kernel<<<1024, 256>>>(G, gmean);                       // 2
    gemm_bulk<EPI_QKV_T, true, 24, false><<<gS, 256, SMEM_TOTAL>>>(   // 3 <-- profiled
        ta, wQKV, bqkv, nullptr, nullptr, nullptr, qkvT, 768,
        nullptr, nullptr, nullptr, nullptr, nullptr, nullptr);
    wconv<<<256, 128>>>(Wp2,  wP2);                             // 4
    // psiT = sigmoid(Wp2 @ relu(v*wp1+bp1) + bp2)^T, A generated in-kernel
    gemm_bulk<EPI_SIG_T, true, 8, true><<<gS, 256, SMEM_TOTAL>>>(
        ta, wP2, bp2, nullptr, nullptr, nullptr, psiT, 256,
        nullptr, nullptr, Vin, Wp1, bp1, nullptr);

    cvec_kernel<<<4, 256>>>(Wout, bout, gmean, cvec);
    tconv<<<tgrid, tblk>>>(Z, tb);
    wconv<<<256, 128>>>(Wk1,  wKV1);
    wconv<<<256, 128>>>(Wv1,  wKV1 + (size_t)256 * KP);
    wconv<<<256, 128>>>(Wk2,  wK2);
    wconv<<<256, 128>>>(Wv2,  wV2);
    wconv<<<256, 128>>>(Wout, wOUT);

    // fused h_k / h_v = relu(W{k1,v1}@Z + b)^T -> tc, td ([px][KP])
    gemm_bulk<EPI_RELU_T, true, 16, false><<<gS, 256, SMEM_TOTAL>>>(
        tb, wKV1, bk1, nullptr, nullptr, nullptr, tc, KP,
        bv1, td, nullptr, nullptr, nullptr, nullptr);

    // kgT = [sigmoid(Wk2@h_k+bk2)*(1-psi)] * K   (pre-gated, fp16)
    gemm_bulk<EPI_SIG_GATE_T, true, 8, false><<<gS, 256, SMEM_TOTAL>>>(
        tc, wK2, bk2, psiT, nullptr, nullptr, kgT, 256,
        nullptr, nullptr, nullptr, nullptr, nullptr, qkvT + 256);
    // vgT = [sigmoid(Wv2@h_v+bv2)*(1-psi)] * V
    gemm_bulk<EPI_SIG_GATE_T, true, 8, false><<<gS, 256, SMEM_TOTAL>>>(
        td, wV2, bv2, psiT, nullptr, nullptr, vgT, 256,
        nullptr, nullptr, nullptr, nullptr, nullptr, qkvT + 512);

    // attention -> ft ([px][KP], reuses tc)
    attn_kernel<<<dim3(4096, 8), 128>>>(qkvT, kgT, vgT, tc);

    // out = 0.5 * Wout @ f + cvec -> fp32 [b][256][HW]
    gemm_bulk<EPI_OUT, false, 8, false><<<gO, 256, SMEM_TOTAL>>>(
        wOUT, tc, nullptr, nullptr, cvec, out, nullptr, 256,
        nullptr, nullptr, nullptr, nullptr, nullptr, nullptr);
}

// round 17
// speedup vs baseline: 1.0278x; 1.0278x over previous
#include <cuda_runtime.h>
#include <cuda_fp16.h>
#include <math.h>
#include <stdint.h>

#define HWSZ 50176           // 224*224
#define BB   4
#define CC   256
#define KP   264             // padded row stride (fp16): 528B = 33*16B
#define KPB  528

// ================= scratch (device globals) =================
__device__ __half g_qkv[(size_t)BB * HWSZ * 768];   // pixel-major [B][HW][768]
__device__ __half g_psi[(size_t)BB * HWSZ * CC];    // [B][HW][256]
__device__ __half g_gk [(size_t)BB * HWSZ * CC];
__device__ __half g_gv [(size_t)BB * HWSZ * CC];
__device__ float  g_mean[BB * CC];
__device__ float  g_cvec[BB * CC];
// fp16 padded operands [B][HW][KP]
__device__ __half g_ta[(size_t)BB * HWSZ * KP];
__device__ __half g_tb[(size_t)BB * HWSZ * KP];
__device__ __half g_tc[(size_t)BB * HWSZ * KP];
__device__ __half g_td[(size_t)BB * HWSZ * KP];
// padded fp16 weights: [qkv 768 | k1 256 | v1 256 | k2 | v2 | p2 | out] x KP
__device__ __half g_wp[2304 * KP];

// ================= PTX helpers =================
__device__ __forceinline__ uint32_t smem_u32(const void* p) {
    uint32_t a;
    asm("{ .reg .u64 t; cvta.to.shared.u64 t, %1; cvt.u32.u64 %0, t; }" : "=r"(a) : "l"(p));
    return a;
}
__device__ __forceinline__ void mbar_init(uint32_t a, uint32_t cnt) {
    asm volatile("mbarrier.init.shared.b64 [%0], %1;" :: "r"(a), "r"(cnt) : "memory");
}
__device__ __forceinline__ void expect_tx(uint32_t mbar, uint32_t bytes) {
    asm volatile("mbarrier.arrive.expect_tx.shared.b64 _, [%0], %1;" :: "r"(mbar), "r"(bytes) : "memory");
}
__device__ __forceinline__ void bulk_g2s(uint32_t dst, const void* src, uint32_t bytes, uint32_t mbar) {
    asm volatile("cp.async.bulk.shared::cluster.global.mbarrier::complete_tx::bytes [%0], [%1], %2, [%3];"
                 :: "r"(dst), "l"(src), "r"(bytes), "r"(mbar) : "memory");
}
__device__ __forceinline__ void mbar_wait(uint32_t mbar, uint32_t parity) {
    asm volatile(
        "{\n\t.reg .pred P;\n"
        "W_%=:\n\t"
        "mbarrier.try_wait.parity.acquire.cta.shared::cta.b64 P, [%0], %1, 0x989680;\n\t"
        "@P bra D_%=;\n\t"
        "bra W_%=;\n"
        "D_%=:\n\t}"
        :: "r"(mbar), "r"(parity) : "memory");
}
#define LDSM4(r0, r1, r2, r3, addr) \
    asm volatile("ldmatrix.sync.aligned.m8n8.x4.shared.b16 {%0,%1,%2,%3}, [%4];" \
                 : "=r"(r0), "=r"(r1), "=r"(r2), "=r"(r3) : "r"(addr))
__device__ __forceinline__ void mma_f16(float* c, const uint32_t* a, uint32_t b0, uint32_t b1) {
    asm volatile(
        "mma.sync.aligned.m16n8k16.row.col.f32.f16.f16.f32 "
        "{%0,%1,%2,%3}, {%4,%5,%6,%7}, {%8,%9}, {%0,%1,%2,%3};"
        : "+f"(c[0]), "+f"(c[1]), "+f"(c[2]), "+f"(c[3])
        : "r"(a[0]), "r"(a[1]), "r"(a[2]), "r"(a[3]), "r"(b0), "r"(b1));
}
__device__ __forceinline__ float sigmoidf_(float x) { return 1.f / (1.f + __expf(-x)); }

// ================= small kernels =================
__global__ void mean_kernel(const float* __restrict__ G, float* __restrict__ out) {
    const int bc = blockIdx.x;
    const float4* p = (const float4*)(G + (size_t)bc * HWSZ);
    float s = 0.f;
    for (int i = threadIdx.x; i < HWSZ / 4; i += blockDim.x) {
        float4 v = p[i];
        s += (v.x + v.y) + (v.z + v.w);
    }
    __shared__ float sm[256];
    sm[threadIdx.x] = s;
    __syncthreads();
    for (int k = 128; k > 0; k >>= 1) {
        if (threadIdx.x < k) sm[threadIdx.x] += sm[threadIdx.x + k];
        __syncthreads();
    }
    if (threadIdx.x == 0) out[bc] = sm[0] * (1.f / HWSZ);
}

__global__ void cvec_kernel(const float* __restrict__ Wout, const float* __restrict__ bout,
                            const float* __restrict__ gmean, float* __restrict__ cvec) {
    __shared__ float gm[CC];
    const int b = blockIdx.x, oc = threadIdx.x;
    gm[oc] = gmean[b * CC + oc];
    __syncthreads();
    float s = 0.f;
    #pragma unroll 8
    for (int c = 0; c < CC; ++c) s += Wout[(size_t)oc * CC + c] * gm[c];
    cvec[b * CC + oc] = 0.5f * s + bout[oc];
}

// ALL fp32 weights -> padded fp16 g_wp in one launch.
// rows: [0,768) qkv | [768,1024) k1 | [1024,1280) v1 | [1280,1536) k2
//       [1536,1792) v2 | [1792,2048) p2 | [2048,2304) out
__global__ void wconv_all(const float* __restrict__ Wqkv, const float* __restrict__ Wk1,
                          const float* __restrict__ Wv1,  const float* __restrict__ Wk2,
                          const float* __restrict__ Wv2,  const float* __restrict__ Wp2,
                          const float* __restrict__ Wout, __half* __restrict__ o) {
    const int row = blockIdx.x, k = threadIdx.x;
    const float* src;
    int lr = row;
    if      (row < 768)  { src = Wqkv; }
    else if (row < 1024) { src = Wk1;  lr = row - 768;  }
    else if (row < 1280) { src = Wv1;  lr = row - 1024; }
    else if (row < 1536) { src = Wk2;  lr = row - 1280; }
    else if (row < 1792) { src = Wv2;  lr = row - 1536; }
    else if (row < 2048) { src = Wp2;  lr = row - 1792; }
    else                 { src = Wout; lr = row - 2048; }
    o[(size_t)row * KP + k]       = __float2half(src[(size_t)lr * 256 + k]);
    o[(size_t)row * KP + k + 128] = __float2half(src[(size_t)lr * 256 + k + 128]);
    if (k < KP - 256) o[(size_t)row * KP + 256 + k] = __float2half(0.f);
}

// transpose fp32 {G,Z}[b][C][HW] -> fp16 padded {ta,tb}[b][HW][KP] in one launch
__global__ void tconv2(const float* __restrict__ G, const float* __restrict__ Z,
                       __half* __restrict__ Ta, __half* __restrict__ Tb) {
    __shared__ float t[32][33];
    const int zz = blockIdx.z;                 // 0..7: tensor = zz>>2, batch = zz&3
    const int b = zz & 3;
    const float* X = (zz < 4) ? G : Z;
    __half* T = (zz < 4) ? Ta : Tb;
    const int k0 = blockIdx.y * 32, p0 = blockIdx.x * 32;
    const int tx = threadIdx.x, ty = threadIdx.y;
    const float* src = X + ((size_t)b * CC + k0) * HWSZ + p0;
    #pragma unroll
    for (int r = 0; r < 4; ++r)
        t[ty + r * 8][tx] = src[(size_t)(ty + r * 8) * HWSZ + tx];
    __syncthreads();
    #pragma unroll
    for (int r = 0; r < 4; ++r) {
        const int p = ty + r * 8;
        T[((size_t)b * HWSZ + p0 + p) * KP + k0 + tx] = __float2half(t[tx][p]);
    }
}

// ================= bulk-copy HMMA GEMM: split warp-group pipeline (R12) =================
enum { EPI_QKV_T = 0, EPI_RELU_T = 1, EPI_SIG_T = 2, EPI_SIG_GATE_T = 3, EPI_OUT = 4 };

#define A_BYTES  (128 * KPB)        // 67584
#define XC_ROWS  32
#define XC_BYTES (XC_ROWS * KPB)    // 16896
#define SM_X0    A_BYTES
#define MB_OFF   (A_BYTES + 2 * XC_BYTES)   // 101376
#define SMEM_TOTAL (MB_OFF + 32)

template<int EPI, bool SWAP, int NCH, bool GENA>
__global__ void __launch_bounds__(256, 2)
gemm_bulk(const __half* __restrict__ A_, const __half* __restrict__ B_,
          const float* __restrict__ bias, const __half* __restrict__ gate,
          const float* __restrict__ cvec, float* __restrict__ Yf,
          __half* __restrict__ Yh, int OS,
          const float* __restrict__ bias2, __half* __restrict__ Yh2,
          const float* __restrict__ gaV, const float* __restrict__ gaW,
          const float* __restrict__ gaB)
{
    extern __shared__ char dsm[];
    const uint32_t smb = smem_u32(dsm);
    const int b = blockIdx.z;
    const int tid = threadIdx.x, wid = tid >> 5, lane = tid & 31;
    const int g = lane >> 2, t = lane & 3;
    const int grp = wid >> 2;          // warp group 0/1
    const int warpM = wid & 3;

    const size_t arow0 = SWAP ? ((size_t)b * HWSZ + (size_t)blockIdx.y * 128)
                              : (size_t)blockIdx.y * 128;
    const size_t brow0 = SWAP ? 0 : ((size_t)b * HWSZ + (size_t)blockIdx.x * (NCH * XC_ROWS));
    const __half* Ab = A_ + arow0 * KP;
    const __half* Bb = B_ + brow0 * KP;

    const uint32_t mbw = smb + MB_OFF;
    const uint32_t mbx = smb + MB_OFF + 8 + (uint32_t)grp * 8;   // group's stage barrier
    if (tid == 0) {
        mbar_init(mbw, 1);
        mbar_init(smb + MB_OFF + 8, 1);
        mbar_init(smb + MB_OFF + 16, 1);
    }
    __syncthreads();
    if (tid == 0) {
        if (!GENA) { expect_tx(mbw, A_BYTES); bulk_g2s(smb, Ab, A_BYTES, mbw); }
        expect_tx(smb + MB_OFF + 8,  XC_BYTES); bulk_g2s(smb + SM_X0,            Bb,                XC_BYTES, smb + MB_OFF + 8);
        expect_tx(smb + MB_OFF + 16, XC_BYTES); bulk_g2s(smb + SM_X0 + XC_BYTES, Bb + XC_ROWS * KP, XC_BYTES, smb + MB_OFF + 16);
    }

    // ldmatrix addresses (528B row stride -> conflict-free)
    const int l7 = lane & 7;
    const uint32_t rowA0 = (uint32_t)(warpM * 32 + l7 + ((lane >> 3) & 1) * 8);
    const uint32_t aA0 = smb + rowA0 * KPB + ((lane >> 4) & 1) * 16;
    const uint32_t aA1 = aA0 + 16 * KPB;
    const uint32_t xb = smb + SM_X0 + (uint32_t)grp * XC_BYTES;  // group's dedicated stage
    const uint32_t rowB0 = (uint32_t)(l7 + ((lane >> 4) & 1) * 8);
    const uint32_t bB0 = xb + rowB0 * KPB + ((lane >> 3) & 1) * 16;
    const uint32_t bB1 = bB0 + 16 * KPB;

    if (GENA) {
        const int r = tid & 127, hf = tid >> 7;
        const float v = gaV[(size_t)b * HWSZ + (size_t)blockIdx.y * 128 + r];
        const int k0 = hf * 132;
        #pragma unroll 1
        for (int kk = 0; kk < 66; ++kk) {
            const int k = k0 + kk * 2;
            float x0 = 0.f, x1 = 0.f;
            if (k < 256) {
                x0 = fmaxf(v * gaW[k]     + gaB[k],     0.f);
                x1 = fmaxf(v * gaW[k + 1] + gaB[k + 1], 0.f);
            }
            __half2 hh; hh.x = __float2half(x0); hh.y = __float2half(x1);
            *(__half2*)(dsm + (size_t)r * KPB + (size_t)k * 2) = hh;
        }
        __syncthreads();
    } else {
        mbar_wait(mbw, 0);
    }

    int ph = 0;
    #pragma unroll 1
    for (int c = grp; c < NCH; c += 2) {
        mbar_wait(mbx, ph);
        ph ^= 1;

        float acc[2][4][4];
        #pragma unroll
        for (int mi = 0; mi < 2; ++mi)
            #pragma unroll
            for (int ni = 0; ni < 4; ++ni)
                #pragma unroll
                for (int u = 0; u < 4; ++u) acc[mi][ni][u] = 0.f;

        #pragma unroll
        for (int k16 = 0; k16 < 16; ++k16) {
            const uint32_t ko = (uint32_t)k16 * 32;
            uint32_t a0[4], a1[4], f0[4], f1[4];
            LDSM4(a0[0], a0[1], a0[2], a0[3], aA0 + ko);
            LDSM4(a1[0], a1[1], a1[2], a1[3], aA1 + ko);
            LDSM4(f0[0], f0[1], f0[2], f0[3], bB0 + ko);
            LDSM4(f1[0], f1[1], f1[2], f1[3], bB1 + ko);
            mma_f16(acc[0][0], a0, f0[0], f0[1]);
            mma_f16(acc[0][1], a0, f0[2], f0[3]);
            mma_f16(acc[0][2], a0, f1[0], f1[1]);
            mma_f16(acc[0][3], a0, f1[2], f1[3]);
            mma_f16(acc[1][0], a1, f0[0], f0[1]);
            mma_f16(acc[1][1], a1, f0[2], f0[3]);
            mma_f16(acc[1][2], a1, f1[0], f1[1]);
            mma_f16(acc[1][3], a1, f1[2], f1[3]);
        }

        asm volatile("bar.sync %0, 128;" :: "r"(grp + 1) : "memory");
        if (c + 2 < NCH && tid == grp * 128) {
            expect_tx(mbx, XC_BYTES);
            bulk_g2s(xb, Bb + (size_t)(c + 2) * XC_ROWS * KP, XC_BYTES, mbx);
        }

        const int nbase = c * XC_ROWS;
        #pragma unroll
        for (int mi = 0; mi < 2; ++mi) {
            #pragma unroll
            for (int r2 = 0; r2 < 2; ++r2) {
                const int m = warpM * 32 + mi * 16 + g + r2 * 8;
                if (!SWAP) {
                    const int oc = (int)blockIdx.y * 128 + m;
                    const float cv = cvec[b * CC + oc];
                    const size_t ybase = ((size_t)b * CC + oc) * HWSZ + (size_t)blockIdx.x * (NCH * XC_ROWS);
                    #pragma unroll
                    for (int ni = 0; ni < 4; ++ni) {
                        const int n = nbase + ni * 8 + t * 2;
                        float2 r;
                        r.x = 0.5f * acc[mi][ni][r2 * 2 + 0] + cv;
                        r.y = 0.5f * acc[mi][ni][r2 * 2 + 1] + cv;
                        *(float2*)(Yf + ybase + n) = r;
                    }
                } else {
                    const size_t prow = (size_t)b * HWSZ + (size_t)blockIdx.y * 128 + m;
                    if (EPI == EPI_RELU_T) {
                        #pragma unroll
                        for (int ni = 0; ni < 4; ++ni) {
                            const int oc = nbase + ni * 8 + t * 2;
                            const float* bp = bias;
                            __half* yp = Yh;
                            int o2 = oc;
                            if (oc >= 256) { bp = bias2; yp = Yh2; o2 = oc - 256; }
                            float v0 = fmaxf(acc[mi][ni][r2 * 2 + 0] + bp[o2], 0.f);
                            float v1 = fmaxf(acc[mi][ni][r2 * 2 + 1] + bp[o2 + 1], 0.f);
                            __half2 r; r.x = __float2half(v0); r.y = __float2half(v1);
                            *(__half2*)(yp + prow * KP + o2) = r;
                        }
                    } else {
                        #pragma unroll
                        for (int ni = 0; ni < 4; ++ni) {
                            const int oc = nbase + ni * 8 + t * 2;
                            float v0 = acc[mi][ni][r2 * 2 + 0] + bias[oc];
                            float v1 = acc[mi][ni][r2 * 2 + 1] + bias[oc + 1];
                            if (EPI == EPI_SIG_T) { v0 = sigmoidf_(v0); v1 = sigmoidf_(v1); }
                            else if (EPI == EPI_SIG_GATE_T) {
                                __half2 gg = *(const __half2*)(gate + prow * CC + oc);
                                v0 = sigmoidf_(v0) * (1.f - __half2float(gg.x));
                                v1 = sigmoidf_(v1) * (1.f - __half2float(gg.y));
                            }
                            __half2 r; r.x = __float2half(v0); r.y = __float2half(v1);
                            *(__half2*)(Yh + prow * OS + oc) = r;
                        }
                    }
                }
            }
        }
    }
}

// ================= windowed attention (R12 exact) =================
__global__ void __launch_bounds__(128)
attn_kernel(const __half* __restrict__ qkvT, const __half* __restrict__ gkT,
            const __half* __restrict__ gvT, __half* __restrict__ ft)
{
    const int w = blockIdx.x, h = blockIdx.y;
    const int b = w >> 10, wy = (w >> 5) & 31, wx = w & 31;
    const int tid = threadIdx.x;

    __shared__ float Qs[49 * 33];
    __shared__ float Ks[49 * 33];
    __shared__ float Vs[49 * 33];
    __shared__ float S [49 * 49];

    const int row0 = wy * 7, col0 = wx * 7;
    const int hoff = h * 32;

    for (int e = tid; e < 49 * 16; e += 128) {
        const int n = e >> 4, d2 = (e & 15) << 1;
        const int hw = (row0 + n / 7) * 224 + col0 + (n % 7);
        const size_t pb = (size_t)b * HWSZ + hw;
        const __half2 q2 = *(const __half2*)(qkvT + pb * 768 + hoff + d2);
        const __half2 k2 = *(const __half2*)(qkvT + pb * 768 + 256 + hoff + d2);
        const __half2 v2 = *(const __half2*)(qkvT + pb * 768 + 512 + hoff + d2);
        const __half2 g2 = *(const __half2*)(gkT + pb * CC + hoff + d2);
        const __half2 u2 = *(const __half2*)(gvT + pb * CC + hoff + d2);
        Qs[n * 33 + d2]     = __half2float(q2.x);
        Qs[n * 33 + d2 + 1] = __half2float(q2.y);
        Ks[n * 33 + d2]     = __half2float(k2.x) * __half2float(g2.x);
        Ks[n * 33 + d2 + 1] = __half2float(k2.y) * __half2float(g2.y);
        Vs[n * 33 + d2]     = __half2float(v2.x) * __half2float(u2.x);
        Vs[n * 33 + d2 + 1] = __half2float(v2.y) * __half2float(u2.y);
    }
    __syncthreads();

    const float scale = 0.17677669529663687f;   // 32^-0.5

    if (tid < 91) {
        const int i0 = (tid / 13) * 7;
        const int j0 = (tid % 13) * 4;
        float acc[7][4];
        #pragma unroll
        for (int r = 0; r < 7; ++r)
            #pragma unroll
            for (int c2 = 0; c2 < 4; ++c2) acc[r][c2] = 0.f;
        int jc[4];
        #pragma unroll
        for (int c2 = 0; c2 < 4; ++c2) jc[c2] = min(j0 + c2, 48);
        #pragma unroll
        for (int d = 0; d < 32; ++d) {
            float kv[4];
            #pragma unroll
            for (int c2 = 0; c2 < 4; ++c2) kv[c2] = Ks[jc[c2] * 33 + d];
            #pragma unroll
            for (int r = 0; r < 7; ++r) {
                const float qv = Qs[(i0 + r) * 33 + d];
                #pragma unroll
                for (int c2 = 0; c2 < 4; ++c2) acc[r][c2] += qv * kv[c2];
            }
        }
        #pragma unroll
        for (int r = 0; r < 7; ++r)
            #pragma unroll
            for (int c2 = 0; c2 < 4; ++c2)
                if (j0 + c2 < 49) S[(i0 + r) * 49 + j0 + c2] = acc[r][c2] * scale;
    }
    __syncthreads();

    if (tid < 49) {
        float m = -1e30f;
        for (int j = 0; j < 49; ++j) m = fmaxf(m, S[tid * 49 + j]);
        float sum = 0.f;
        for (int j = 0; j < 49; ++j) {
            float ev = __expf(S[tid * 49 + j] - m);
            S[tid * 49 + j] = ev;
            sum += ev;
        }
        const float inv = 1.f / sum;
        for (int j = 0; j < 49; ++j) S[tid * 49 + j] *= inv;
    }
    __syncthreads();

    if (tid < 104) {
        const int n0 = (tid / 8) * 4;
        const int d0 = (tid & 7) * 4;
        float acc[4][4];
        #pragma unroll
        for (int r = 0; r < 4; ++r)
            #pragma unroll
            for (int c2 = 0; c2 < 4; ++c2) acc[r][c2] = 0.f;
        int nr[4];
        #pragma unroll
        for (int r = 0; r < 4; ++r) nr[r] = min(n0 + r, 48);
        #pragma unroll 7
        for (int m2 = 0; m2 < 49; ++m2) {
            float vv[4];
            #pragma unroll
            for (int c2 = 0; c2 < 4; ++c2) vv[c2] = Vs[m2 * 33 + d0 + c2];
            #pragma unroll
            for (int r = 0; r < 4; ++r) {
                const float sv = S[nr[r] * 49 + m2];
                #pragma unroll
                for (int c2 = 0; c2 < 4; ++c2) acc[r][c2] += sv * vv[c2];
            }
        }
        #pragma unroll
        for (int r = 0; r < 4; ++r) {
            const int n = n0 + r;
            if (n < 49) {
                const int hw = (row0 + n / 7) * 224 + col0 + (n % 7);
                #pragma unroll
                for (int c2 = 0; c2 < 4; ++c2)
                    ft[((size_t)b * HWSZ + hw) * KP + hoff + d0 + c2] = __float2half(acc[r][c2]);
            }
        }
    }
}

// ================= launcher =================
extern "C" void kernel_launch(void* const* d_in, const int* in_sizes, int n_in,
                              void* d_out, int out_size) {
    (void)in_sizes; (void)n_in; (void)out_size;
    const float* G    = (const float*)d_in[0];
    const float* Vin  = (const float*)d_in[2];
    const float* Z    = (const float*)d_in[3];
    const float* Wqkv = (const float*)d_in[4];
    const float* bqkv = (const float*)d_in[5];
    const float* Wout = (const float*)d_in[6];
    const float* bout = (const float*)d_in[7];
    const float* Wk1  = (const float*)d_in[8];
    const float* bk1  = (const float*)d_in[9];
    const float* Wk2  = (const float*)d_in[10];
    const float* bk2  = (const float*)d_in[11];
    const float* Wv1  = (const float*)d_in[12];
    const float* bv1  = (const float*)d_in[13];
    const float* Wv2  = (const float*)d_in[14];
    const float* bv2  = (const float*)d_in[15];
    const float* Wp1  = (const float*)d_in[16];
    const float* bp1  = (const float*)d_in[17];
    const float* Wp2  = (const float*)d_in[18];
    const float* bp2  = (const float*)d_in[19];
    float* out = (float*)d_out;

    __half *qkvT, *psiT, *gkT, *gvT, *ta, *tb, *tc, *td, *wp;
    float *gmean, *cvec;
    cudaGetSymbolAddress((void**)&qkvT,  g_qkv);
    cudaGetSymbolAddress((void**)&psiT,  g_psi);
    cudaGetSymbolAddress((void**)&gkT,   g_gk);
    cudaGetSymbolAddress((void**)&gvT,   g_gv);
    cudaGetSymbolAddress((void**)&gmean, g_mean);
    cudaGetSymbolAddress((void**)&cvec,  g_cvec);
    cudaGetSymbolAddress((void**)&ta,    g_ta);
    cudaGetSymbolAddress((void**)&tb,    g_tb);
    cudaGetSymbolAddress((void**)&tc,    g_tc);
    cudaGetSymbolAddress((void**)&td,    g_td);
    cudaGetSymbolAddress((void**)&wp,    g_wp);

    cudaFuncSetAttribute(gemm_bulk<EPI_QKV_T,      true,  24, false>, cudaFuncAttributeMaxDynamicSharedMemorySize, SMEM_TOTAL);
    cudaFuncSetAttribute(gemm_bulk<EPI_RELU_T,     true,  16, false>, cudaFuncAttributeMaxDynamicSharedMemorySize, SMEM_TOTAL);
    cudaFuncSetAttribute(gemm_bulk<EPI_SIG_T,      true,  8,  true>,  cudaFuncAttributeMaxDynamicSharedMemorySize, SMEM_TOTAL);
    cudaFuncSetAttribute(gemm_bulk<EPI_SIG_GATE_T, true,  8,  false>, cudaFuncAttributeMaxDynamicSharedMemorySize, SMEM_TOTAL);
    cudaFuncSetAttribute(gemm_bulk<EPI_OUT,        false, 8,  false>, cudaFuncAttributeMaxDynamicSharedMemorySize, SMEM_TOTAL);

    // weight layout (rows of KP)
    __half* wQKV = wp;
    __half* wKV1 = wp + (size_t)768  * KP;   // k1 rows [0,256), v1 rows [256,512)
    __half* wK2  = wp + (size_t)1280 * KP;
    __half* wV2  = wp + (size_t)1536 * KP;
    __half* wP2  = wp + (size_t)1792 * KP;
    __half* wOUT = wp + (size_t)2048 * KP;

    const dim3 t2grid(HWSZ / 32, CC / 32, 2 * BB), tblk(32, 8);
    const dim3 gS(1, 392, BB);    // SWAP: px-tiles(128) on y
    const dim3 gO(196, 2, BB);    // !SWAP out: px-tiles(256) x oc-tiles(128) x B

    // launch order: index 3 = qkv GEMM (ncu profiled slot)
    tconv2<<<t2grid, tblk>>>(G, Z, ta, tb);                     // 0 (G->ta, Z->tb)
    wconv_all<<<2304, 128>>>(Wqkv, Wk1, Wv1, Wk2, Wv2, Wp2, Wout, wp);  // 1
    mean_kernel<<<1024, 256>>>(G, gmean);                       // 2
    gemm_bulk<EPI_QKV_T, true, 24, false><<<gS, 256, SMEM_TOTAL>>>(   // 3 <-- profiled
        ta, wQKV, bqkv, nullptr, nullptr, nullptr, qkvT, 768,
        nullptr, nullptr, nullptr, nullptr, nullptr);
    // psiT = sigmoid(Wp2 @ relu(v*wp1+bp1) + bp2)^T, A generated in-kernel
    gemm_bulk<EPI_SIG_T, true, 8, true><<<gS, 256, SMEM_TOTAL>>>(     // 4
        ta, wP2, bp2, nullptr, nullptr, nullptr, psiT, 256,
        nullptr, nullptr, Vin, Wp1, bp1);
    cvec_kernel<<<4, 256>>>(Wout, bout, gmean, cvec);           // 5

    // fused h_k / h_v = relu(W{k1,v1}@Z + b)^T -> tc, td ([px][KP])
    gemm_bulk<EPI_RELU_T, true, 16, false><<<gS, 256, SMEM_TOTAL>>>(
        tb, wKV1, bk1, nullptr, nullptr, nullptr, tc, KP,
        bv1, td, nullptr, nullptr, nullptr);

    // gkT = sigmoid(Wk2@h_k+bk2)^T * (1-psiT); gvT likewise
    gemm_bulk<EPI_SIG_GATE_T, true, 8, false><<<gS, 256, SMEM_TOTAL>>>(
        tc, wK2, bk2, psiT, nullptr, nullptr, gkT, 256,
        nullptr, nullptr, nullptr, nullptr, nullptr);
    gemm_bulk<EPI_SIG_GATE_T, true, 8, false><<<gS, 256, SMEM_TOTAL>>>(
        td, wV2, bv2, psiT, nullptr, nullptr, gvT, 256,
        nullptr, nullptr, nullptr, nullptr, nullptr);

    // attention -> ft ([px][KP], reuses tc)
    attn_kernel<<<dim3(4096, 8), 128>>>(qkvT, gkT, gvT, tc);

    // out = 0.5 * Wout @ f + cvec -> fp32 [b][256][HW]
    gemm_bulk<EPI_OUT, false, 8, false><<<gO, 256, SMEM_TOTAL>>>(
        wOUT, tc, nullptr, nullptr, cvec, out, nullptr, 256,
        nullptr, nullptr, nullptr, nullptr, nullptr);
}